// round 1
// baseline (speedup 1.0000x reference)
#include <cuda_runtime.h>

// PatternDetector: per-row streaming features over compacted nonzero tokens.
// B=131072 rows, L=256 int32 tokens in [0,40). Output B x 4 float32.
//
// Key insight: the reference's stable argsort merely moves nonzeros to the
// front in original order. Every feature is a function of consecutive
// nonzero values, so a single forward scan with (prev1, prev2) suffices.

constexpr int L_LEN  = 256;   // tokens per row
constexpr int ROWS   = 128;   // rows per block (= threads per block)
constexpr int SROW   = 260;   // padded bytes per smem row (65 words -> conflict-free)

__global__ __launch_bounds__(ROWS) void pattern_kernel(
    const int4* __restrict__ x4, float4* __restrict__ out)
{
    __shared__ unsigned char s[ROWS * SROW];
    const int tid = threadIdx.x;

    // ---- Stage: coalesced gmem -> byte-packed smem ----
    // Block region: ROWS*L_LEN ints = 8192 int4, 64 per thread.
    const long long base4 = (long long)blockIdx.x * (ROWS * L_LEN / 4);
    const int4* src = x4 + base4;

    #pragma unroll 4
    for (int it = 0; it < (ROWS * L_LEN / 4) / ROWS; ++it) {
        int idx  = it * ROWS + tid;            // int4 index within block region
        int4 v   = src[idx];
        int elem = idx << 2;                   // element index
        int row  = elem >> 8;                  // / L_LEN
        int col  = elem & (L_LEN - 1);
        // values < 40 -> pack 4 ints into 4 bytes
        unsigned int packed = (unsigned)v.x | ((unsigned)v.y << 8)
                            | ((unsigned)v.z << 16) | ((unsigned)v.w << 24);
        *(unsigned int*)&s[row * SROW + col] = packed;
    }
    __syncthreads();

    // ---- Scan: one thread per row, branchless ----
    const unsigned int* row = (const unsigned int*)&s[tid * SROW];
    int prev1 = -1, prev2 = -1;
    int rep = 0, inc = 0, dec = 0, per = 0, n = 0;

    #pragma unroll 8
    for (int i = 0; i < L_LEN / 4; ++i) {
        unsigned int w = row[i];
        #pragma unroll
        for (int k = 0; k < 4; ++k) {
            int v = (w >> (k * 8)) & 0xff;
            bool nz   = (v != 0);
            bool hasp = (prev1 >= 0);
            // prev1/prev2 are never 0, so equality tests need no nz-guard
            rep += (v == prev1);
            per += (v == prev2);
            inc += (int)(nz & hasp & (v > prev1));
            dec += (int)(nz & hasp & (v < prev1));
            n   += (int)nz;
            prev2 = nz ? prev1 : prev2;
            prev1 = nz ? v     : prev1;
        }
    }

    // ---- Epilogue ----
    float f0 = 0.f, f1 = 0.f, f2 = 0.f, f3 = 0.f;
    if (n > 1) {
        float d1 = (float)(n - 1);
        f0 = (float)rep / d1;
        f1 = (float)inc / d1;
        f2 = (float)dec / d1;
        if (n >= 4) {
            float d2 = (float)(n - 2);
            f3 = (float)per / d2;
        }
    }
    out[blockIdx.x * ROWS + tid] = make_float4(f0, f1, f2, f3);
}

extern "C" void kernel_launch(void* const* d_in, const int* in_sizes, int n_in,
                              void* d_out, int out_size)
{
    const int4* x  = (const int4*)d_in[0];
    float4* out    = (float4*)d_out;
    const int total_elems = in_sizes[0];          // B * L
    const int nrows  = total_elems / L_LEN;       // 131072
    const int blocks = nrows / ROWS;              // 1024
    pattern_kernel<<<blocks, ROWS>>>(x, out);
}

// round 2
// speedup vs baseline: 1.1975x; 1.1975x over previous
#include <cuda_runtime.h>

// PatternDetector: B=131072 rows x L=256 int32 tokens in [0,40). Output Bx4 f32.
//
// The reference's stable "nonzeros first" argsort preserves order, so all
// features are functions of consecutive-nonzero pairs. We split each row into
// 4 chunks of 64 elements, scan each chunk with a short dependency chain, and
// merge chunk states with shfl_xor.
//
// Sentinels: prev1/prev2 init = 127 (values are <40, zeros never compared as
// prev since prev only takes nonzero values) -> no validity guards needed:
//   v==prev  : false for v=0 (prev never 0) and for prev=127 (v<40)
//   v >prev  : false for v=0 (prev>=1) and for prev=127 (v<40)
// f1/f2 sentinel = 0 (first/second nonzero are >=1).
// dec is derived: every consecutive-nonzero pair is exactly one of ==,>,< so
// dec = (n-1) - rep - inc.

constexpr int L_LEN  = 256;
constexpr int CHUNKS = 4;                 // threads per row
constexpr int CELEMS = L_LEN / CHUNKS;    // 64 elements per thread
constexpr int TPB    = 256;

__global__ __launch_bounds__(TPB) void pattern_kernel(
    const int4* __restrict__ x4, float4* __restrict__ out)
{
    const int g    = blockIdx.x * TPB + threadIdx.x;
    const int row  = g >> 2;
    const int c    = g & 3;
    const int lane = threadIdx.x & 31;

    const int4* src = x4 + (long long)row * (L_LEN / 4) + c * (CELEMS / 4);

    int prev1 = 127, prev2 = 127;   // last / second-to-last nonzero (sentinel 127)
    int f1 = 0, f2 = 0;             // first / second nonzero (sentinel 0)
    int n = 0, rep = 0, inc = 0, per = 0;

    // ---- chunk scan: 16 x LDG.128, fully coalesced (warp covers 8 rows) ----
    #pragma unroll 4
    for (int w = 0; w < CELEMS / 4; ++w) {
        int4 q = src[w];
        int vv[4] = {q.x, q.y, q.z, q.w};
        #pragma unroll
        for (int k = 0; k < 4; ++k) {
            int v = vv[k];
            bool nz = (v != 0);
            rep += (v == prev1);
            inc += (v >  prev1);
            per += (v == prev2);
            f2 = (nz && n == 1) ? v : f2;
            f1 = (nz && n == 0) ? v : f1;
            n += nz;
            prev2 = nz ? prev1 : prev2;
            prev1 = nz ? v     : prev1;
        }
    }

    // ---- pack state ----
    // A = n | rep<<16 ; B = inc | per<<16 ; F = f1 | f2<<8 ; Lw = l1 | l2<<8
    unsigned A  = (unsigned)n   | ((unsigned)rep << 16);
    unsigned B  = (unsigned)inc | ((unsigned)per << 16);
    unsigned F  = (unsigned)f1  | ((unsigned)f2  << 8);
    unsigned Lw = (unsigned)prev1 | ((unsigned)prev2 << 8);

    // ---- tree merge across the 4 chunk lanes (xor 1, then xor 2) ----
    #pragma unroll
    for (int m = 1; m <= 2; m <<= 1) {
        unsigned A2  = __shfl_xor_sync(0xffffffffu, A,  m);
        unsigned B2  = __shfl_xor_sync(0xffffffffu, B,  m);
        unsigned F2  = __shfl_xor_sync(0xffffffffu, F,  m);
        unsigned L2  = __shfl_xor_sync(0xffffffffu, Lw, m);
        bool left = ((lane & m) == 0);

        unsigned AL = left ? A  : A2,  AR = left ? A2 : A;
        unsigned BL = left ? B  : B2,  BR = left ? B2 : B;
        unsigned FL = left ? F  : F2,  FR = left ? F2 : F;
        unsigned LL = left ? Lw : L2,  LR = left ? L2 : Lw;

        int l1L = LL & 0xff, l2L = (LL >> 8) & 0xff;
        int l1R = LR & 0xff, l2R = (LR >> 8) & 0xff;
        int f1L = FL & 0xff, f2L = (FL >> 8) & 0xff;
        int f1R = FR & 0xff, f2R = (FR >> 8) & 0xff;

        unsigned crossRep = (unsigned)(l1L == f1R);              // 127 / 0 sentinels safe
        unsigned crossInc = (unsigned)(f1R >  l1L);
        unsigned crossPer = (unsigned)(l2L == f1R) + (unsigned)(l1L == f2R);

        A = AL + AR + (crossRep << 16);
        B = BL + BR + crossInc + (crossPer << 16);

        int nf1 = f1L ? f1L : f1R;
        int nf2 = f2L ? f2L : (f1L ? f1R : f2R);
        F = (unsigned)nf1 | ((unsigned)nf2 << 8);

        int nl1 = (l1R != 127) ? l1R : l1L;
        int nl2 = (l2R != 127) ? l2R : ((l1R != 127) ? l1L : l2L);
        Lw = (unsigned)nl1 | ((unsigned)nl2 << 8);
    }

    // ---- epilogue: lane c==0 of each group writes the row ----
    if (c == 0) {
        int N   = (int)(A & 0xffffu);
        int REP = (int)(A >> 16);
        int INC = (int)(B & 0xffffu);
        int PER = (int)(B >> 16);
        float o0 = 0.f, o1 = 0.f, o2 = 0.f, o3 = 0.f;
        if (N > 1) {
            int DEC = (N - 1) - REP - INC;
            float d1 = 1.0f / (float)(N - 1);
            o0 = (float)REP * d1;
            o1 = (float)INC * d1;
            o2 = (float)DEC * d1;
            if (N >= 4) o3 = (float)PER / (float)(N - 2);
        }
        out[row] = make_float4(o0, o1, o2, o3);
    }
}

extern "C" void kernel_launch(void* const* d_in, const int* in_sizes, int n_in,
                              void* d_out, int out_size)
{
    const int4* x = (const int4*)d_in[0];
    float4* out   = (float4*)d_out;
    const int total_elems = in_sizes[0];           // B * L
    const int nrows  = total_elems / L_LEN;        // 131072
    const int blocks = (nrows * CHUNKS) / TPB;     // 2048
    pattern_kernel<<<blocks, TPB>>>(x, out);
}

// round 3
// speedup vs baseline: 1.3638x; 1.1388x over previous
#include <cuda_runtime.h>

// PatternDetector: B=131072 rows x L=256 int32 in [0,40). Output Bx4 f32.
//
// Stable "nonzeros-first" argsort preserves order -> all features are
// functions of consecutive-nonzero pairs -> single forward scan per row.
//
// Layout: block of 256 threads stages 64 rows via coalesced int4 loads,
// packs values (<40) to bytes in smem. Each thread scans one 64-byte chunk
// (4 chunks per row). Instead of segment-merge bookkeeping, each thread
// initializes its (prev1, prev2) by peeking backward in smem across the
// chunk boundary (expected ~2 byte probes). Chunk counters then sum exactly.
//
// Sentinel 127 for prev1/prev2 (values < 40, and prev only ever takes
// nonzero values) makes all guards vanish:
//   v==prev : false for v=0 (prev never 0) and prev=127 (v<40)
//   v> prev : false for v=0 (prev>=1)      and prev=127 (v<40)
// dec = (n-1) - rep - inc  (each compacted-adjacent pair is ==, > or <).

constexpr int TPB     = 256;   // threads per block = chunks per block
constexpr int RPB     = 64;    // rows per block
constexpr int L_LEN   = 256;
constexpr int CSTRIDE = 80;    // bytes per 64B chunk slot (20 words: LDS.128
                               // conflict-free, 16B aligned)

__global__ __launch_bounds__(TPB) void pattern_kernel(
    const int4* __restrict__ x4, float4* __restrict__ out)
{
    __shared__ unsigned char s[TPB * CSTRIDE];   // 20480 B
    const int tid = threadIdx.x;

    // ---- Stage: coalesced gmem -> byte-packed smem ----
    // Block region: 64 rows * 64 int4 = 4096 int4; 16 per thread.
    const int4* src = x4 + (long long)blockIdx.x * (RPB * L_LEN / 4);
    #pragma unroll
    for (int it = 0; it < 16; ++it) {
        int idx = it * TPB + tid;              // int4 index (warp-contiguous)
        int4 v  = src[idx];
        unsigned packed = (unsigned)v.x | ((unsigned)v.y << 8)
                        | ((unsigned)v.z << 16) | ((unsigned)v.w << 24);
        int q = idx >> 4;                      // chunk index (16 int4/chunk)
        int w = idx & 15;                      // word within chunk
        *(unsigned*)&s[q * CSTRIDE + w * 4] = packed;
    }
    __syncthreads();

    // ---- Init prev1/prev2 by peeking backward across the chunk boundary ----
    const int c         = tid & 3;             // chunk within row
    const int row_chunk = tid & ~3;            // first chunk of this row
    int prev1 = 127, prev2 = 127;
    if (c) {
        int j = c * 64 - 1, found = 0;
        while (j >= 0 && found < 2) {          // expected ~2 iterations
            int v = s[(row_chunk + (j >> 6)) * CSTRIDE + (j & 63)];
            if (v) { if (!found) prev1 = v; else prev2 = v; ++found; }
            --j;
        }
    }

    // ---- Scan this thread's 64-byte chunk (4 x LDS.128) ----
    const uint4* chunk = (const uint4*)&s[tid * CSTRIDE];
    int n = 0, rep = 0, inc = 0, per = 0;
    #pragma unroll
    for (int i = 0; i < 4; ++i) {
        uint4 q4 = chunk[i];
        unsigned ws[4] = {q4.x, q4.y, q4.z, q4.w};
        #pragma unroll
        for (int wi = 0; wi < 4; ++wi) {
            unsigned w = ws[wi];
            #pragma unroll
            for (int k = 0; k < 4; ++k) {
                int v = (w >> (8 * k)) & 0xff;
                bool nz = (v != 0);
                rep += (v == prev1);
                inc += (v >  prev1);
                per += (v == prev2);
                n   += nz;
                prev2 = nz ? prev1 : prev2;
                prev1 = nz ? v     : prev1;
            }
        }
    }

    // ---- Reduce the 4 chunk lanes (counters sum exactly) ----
    unsigned A = (unsigned)n   | ((unsigned)rep << 16);
    unsigned B = (unsigned)inc | ((unsigned)per << 16);
    A += __shfl_xor_sync(0xffffffffu, A, 1);
    B += __shfl_xor_sync(0xffffffffu, B, 1);
    A += __shfl_xor_sync(0xffffffffu, A, 2);
    B += __shfl_xor_sync(0xffffffffu, B, 2);

    if (c == 0) {
        int N   = (int)(A & 0xffffu);
        int REP = (int)(A >> 16);
        int INC = (int)(B & 0xffffu);
        int PER = (int)(B >> 16);
        float o0 = 0.f, o1 = 0.f, o2 = 0.f, o3 = 0.f;
        if (N > 1) {
            int DEC  = (N - 1) - REP - INC;
            float d1 = 1.0f / (float)(N - 1);
            o0 = (float)REP * d1;
            o1 = (float)INC * d1;
            o2 = (float)DEC * d1;
            if (N >= 4) o3 = (float)PER / (float)(N - 2);
        }
        out[(long long)blockIdx.x * RPB + (tid >> 2)] =
            make_float4(o0, o1, o2, o3);
    }
}

extern "C" void kernel_launch(void* const* d_in, const int* in_sizes, int n_in,
                              void* d_out, int out_size)
{
    const int4* x = (const int4*)d_in[0];
    float4* out   = (float4*)d_out;
    const int total_elems = in_sizes[0];      // B * L
    const int nrows  = total_elems / L_LEN;   // 131072
    const int blocks = nrows / RPB;           // 2048
    pattern_kernel<<<blocks, TPB>>>(x, out);
}

// round 4
// speedup vs baseline: 1.5788x; 1.1577x over previous
#include <cuda_runtime.h>

// PatternDetector: B=131072 rows x L=256 int32 in [0,40). Output Bx4 f32.
//
// Stable "nonzeros-first" argsort preserves order -> all features are
// functions of consecutive-nonzero pairs -> single forward scan per row.
// Sentinel 127 for prev1/prev2 kills all validity guards (values < 40,
// prev only ever holds nonzeros). dec = (n-1) - rep - inc.
//
// R4: two independent 32-element chains per thread (ILP / halved SEL chain),
// register-based init for chain B, word fast-path for the cross-thread peek,
// phased LDS preload.

constexpr int TPB     = 256;
constexpr int RPB     = 64;
constexpr int L_LEN   = 256;
constexpr int CSTRIDE = 80;    // 64B chunk in 20-word slot: LDS.128 conflict-free

// branchless "last two nonzeros" of a 4-byte word (forward order = ascending pos)
__device__ __forceinline__ void last2nz_word(unsigned w, int& p1, int& p2, int& cnt)
{
    p1 = 0; p2 = 0; cnt = 0;
    #pragma unroll
    for (int k = 0; k < 4; ++k) {
        int v = (w >> (8 * k)) & 0xff;
        bool nz = (v != 0);
        p2 = nz ? p1 : p2;
        p1 = nz ? v  : p1;
        cnt += nz;
    }
}

__global__ void __launch_bounds__(TPB, 5) pattern_kernel(
    const int4* __restrict__ x4, float4* __restrict__ out)
{
    __shared__ unsigned char s[TPB * CSTRIDE];   // 20480 B
    const int tid = threadIdx.x;

    // ---- Stage: coalesced gmem -> byte-packed smem ----
    const int4* src = x4 + (long long)blockIdx.x * (RPB * L_LEN / 4);
    #pragma unroll
    for (int it = 0; it < 16; ++it) {
        int idx = it * TPB + tid;
        int4 v  = src[idx];
        unsigned packed = (unsigned)v.x | ((unsigned)v.y << 8)
                        | ((unsigned)v.z << 16) | ((unsigned)v.w << 24);
        *(unsigned*)&s[(idx >> 4) * CSTRIDE + (idx & 15) * 4] = packed;
    }
    __syncthreads();

    const int c         = tid & 3;      // chunk within row
    const int row_chunk = tid & ~3;

    // ---- Preload phase 1 ----
    const uint4* chunk = (const uint4*)&s[tid * CSTRIDE];
    uint4 q0 = chunk[0];
    uint4 q2 = chunk[2];

    // ---- Chain A init: last 2 nonzeros before element c*64 ----
    int a1 = 127, a2 = 127;
    if (c) {
        // fast path: last word of the previous chunk (elements c*64-4 .. c*64-1)
        unsigned w = *(const unsigned*)&s[(tid - 1) * CSTRIDE + 60];
        int p1, p2, cnt;
        last2nz_word(w, p1, p2, cnt);
        if (cnt >= 2) { a1 = p1; a2 = p2; }
        else {
            int j = c * 64 - 1, found = 0;
            while (j >= 0 && found < 2) {
                int v = s[(row_chunk + (j >> 6)) * CSTRIDE + (j & 63)];
                if (v) { if (!found) a1 = v; else a2 = v; ++found; }
                --j;
            }
        }
    }

    // ---- Preload phase 2 ----
    uint4 q1 = chunk[1];
    uint4 q3 = chunk[3];

    // ---- Chain B init: last 2 nonzeros before element c*64+32 ----
    // Fast path from register q1.w (elements 28..31 of this chunk).
    int b1 = 127, b2 = 127;
    {
        int p1, p2, cnt;
        last2nz_word(q1.w, p1, p2, cnt);
        if (cnt >= 2) { b1 = p1; b2 = p2; }
        else {
            int j = c * 64 + 31, found = 0;
            while (j >= 0 && found < 2) {
                int v = s[(row_chunk + (j >> 6)) * CSTRIDE + (j & 63)];
                if (v) { if (!found) b1 = v; else b2 = v; ++found; }
                --j;
            }
        }
    }

    // ---- Dual-chain scan: A over q0,q1 ; B over q2,q3 (interleaved) ----
    int nA = 0, repA = 0, incA = 0, perA = 0;
    int nB = 0, repB = 0, incB = 0, perB = 0;

    unsigned WA[8] = {q0.x, q0.y, q0.z, q0.w, q1.x, q1.y, q1.z, q1.w};
    unsigned WB[8] = {q2.x, q2.y, q2.z, q2.w, q3.x, q3.y, q3.z, q3.w};

    #pragma unroll
    for (int w = 0; w < 8; ++w) {
        unsigned wa = WA[w], wb = WB[w];
        #pragma unroll
        for (int k = 0; k < 4; ++k) {
            int va = (wa >> (8 * k)) & 0xff;
            int vb = (wb >> (8 * k)) & 0xff;
            bool nza = (va != 0);
            bool nzb = (vb != 0);
            repA += (va == a1);   repB += (vb == b1);
            incA += (va >  a1);   incB += (vb >  b1);
            perA += (va == a2);   perB += (vb == b2);
            nA   += nza;          nB   += nzb;
            a2 = nza ? a1 : a2;   b2 = nzb ? b1 : b2;
            a1 = nza ? va : a1;   b1 = nzb ? vb : b1;
        }
    }

    // ---- Reduce the 4 chunk lanes (counters sum exactly) ----
    unsigned A = (unsigned)(nA + nB)     | ((unsigned)(repA + repB) << 16);
    unsigned B = (unsigned)(incA + incB) | ((unsigned)(perA + perB) << 16);
    A += __shfl_xor_sync(0xffffffffu, A, 1);
    B += __shfl_xor_sync(0xffffffffu, B, 1);
    A += __shfl_xor_sync(0xffffffffu, A, 2);
    B += __shfl_xor_sync(0xffffffffu, B, 2);

    if (c == 0) {
        int N   = (int)(A & 0xffffu);
        int REP = (int)(A >> 16);
        int INC = (int)(B & 0xffffu);
        int PER = (int)(B >> 16);
        float o0 = 0.f, o1 = 0.f, o2 = 0.f, o3 = 0.f;
        if (N > 1) {
            int DEC  = (N - 1) - REP - INC;
            float d1 = 1.0f / (float)(N - 1);
            o0 = (float)REP * d1;
            o1 = (float)INC * d1;
            o2 = (float)DEC * d1;
            if (N >= 4) o3 = (float)PER / (float)(N - 2);
        }
        out[(long long)blockIdx.x * RPB + (tid >> 2)] =
            make_float4(o0, o1, o2, o3);
    }
}

extern "C" void kernel_launch(void* const* d_in, const int* in_sizes, int n_in,
                              void* d_out, int out_size)
{
    const int4* x = (const int4*)d_in[0];
    float4* out   = (float4*)d_out;
    const int total_elems = in_sizes[0];      // B * L
    const int nrows  = total_elems / L_LEN;   // 131072
    const int blocks = nrows / RPB;           // 2048
    pattern_kernel<<<blocks, TPB>>>(x, out);
}

// round 5
// speedup vs baseline: 1.8323x; 1.1606x over previous
#include <cuda_runtime.h>
#include <cuda_fp16.h>

// PatternDetector: B=131072 rows x L=256 int32 in [0,40). Output Bx4 f32.
//
// Stable "nonzeros-first" argsort preserves order -> all features are
// functions of consecutive-nonzero pairs -> single forward scan per row.
// dec = (n-1) - rep - inc.
//
// R5: SIMD the two independent 32-element chains (per thread) into ONE half2
// chain. Values v<40 are carried as half 1024+v (bits 0x6400|v, exact).
// Compares via __heq2/__hgt2/__hne2 (1.0/0.0 masks), counters via __hadd2,
// prev updates via exact __hfma2 blends. ~7 inst/element, mostly FMA-pipe.
// Sentinel 127 -> 1151.0: never equal to any v (<=1063), never less.

constexpr int TPB     = 256;
constexpr int RPB     = 64;
constexpr int L_LEN   = 256;
constexpr int CSTRIDE = 80;    // 64B chunk in 20-word slot: LDS.128 conflict-free

__device__ __forceinline__ __half2 h2bits(unsigned u) {
    return *reinterpret_cast<__half2*>(&u);
}
__device__ __forceinline__ unsigned bitsh2(__half2 h) {
    return *reinterpret_cast<unsigned*>(&h);
}

// branchless "last two nonzeros" of a 4-byte word (ascending position order)
__device__ __forceinline__ void last2nz_word(unsigned w, int& p1, int& p2, int& cnt)
{
    p1 = 0; p2 = 0; cnt = 0;
    #pragma unroll
    for (int k = 0; k < 4; ++k) {
        int v = (w >> (8 * k)) & 0xff;
        bool nz = (v != 0);
        p2 = nz ? p1 : p2;
        p1 = nz ? v  : p1;
        cnt += nz;
    }
}

__global__ void __launch_bounds__(TPB, 5) pattern_kernel(
    const int4* __restrict__ x4, float4* __restrict__ out)
{
    __shared__ unsigned char s[TPB * CSTRIDE];   // 20480 B
    const int tid = threadIdx.x;

    // ---- Stage: coalesced gmem -> byte-packed smem ----
    const int4* src = x4 + (long long)blockIdx.x * (RPB * L_LEN / 4);
    #pragma unroll
    for (int it = 0; it < 16; ++it) {
        int idx = it * TPB + tid;
        int4 v  = src[idx];
        unsigned packed = (unsigned)v.x | ((unsigned)v.y << 8)
                        | ((unsigned)v.z << 16) | ((unsigned)v.w << 24);
        *(unsigned*)&s[(idx >> 4) * CSTRIDE + (idx & 15) * 4] = packed;
    }
    __syncthreads();

    const int c         = tid & 3;      // chunk within row
    const int row_chunk = tid & ~3;

    // ---- Preload phase 1 ----
    const uint4* chunk = (const uint4*)&s[tid * CSTRIDE];
    uint4 q0 = chunk[0];
    uint4 q2 = chunk[2];

    // ---- Chain A init: last 2 nonzeros before element c*64 ----
    int a1 = 127, a2 = 127;
    if (c) {
        unsigned w = *(const unsigned*)&s[(tid - 1) * CSTRIDE + 60];
        int p1, p2, cnt;
        last2nz_word(w, p1, p2, cnt);
        if (cnt >= 2) { a1 = p1; a2 = p2; }
        else {
            int j = c * 64 - 1, found = 0;
            while (j >= 0 && found < 2) {
                int v = s[(row_chunk + (j >> 6)) * CSTRIDE + (j & 63)];
                if (v) { if (!found) a1 = v; else a2 = v; ++found; }
                --j;
            }
        }
    }

    // ---- Preload phase 2 ----
    uint4 q1 = chunk[1];
    uint4 q3 = chunk[3];

    // ---- Chain B init: last 2 nonzeros before element c*64+32 ----
    int b1 = 127, b2 = 127;
    {
        int p1, p2, cnt;
        last2nz_word(q1.w, p1, p2, cnt);   // elements 28..31 of this chunk
        if (cnt >= 2) { b1 = p1; b2 = p2; }
        else {
            int j = c * 64 + 31, found = 0;
            while (j >= 0 && found < 2) {
                int v = s[(row_chunk + (j >> 6)) * CSTRIDE + (j & 63)];
                if (v) { if (!found) b1 = v; else b2 = v; ++found; }
                --j;
            }
        }
    }

    // ---- Half2 chain state: low half = chain A, high half = chain B ----
    const unsigned BIAS = 0x64006400u;    // half2 {1024, 1024}
    const unsigned BMSK = 0x00FF00FFu;
    __half2 p1h = h2bits(((unsigned)(0x6400 | a1)) | ((unsigned)(0x6400 | b1) << 16));
    __half2 p2h = h2bits(((unsigned)(0x6400 | a2)) | ((unsigned)(0x6400 | b2) << 16));
    __half2 zero1024 = h2bits(BIAS);
    __half2 accR = h2bits(0u), accI = h2bits(0u);
    __half2 accP = h2bits(0u), accN = h2bits(0u);

    unsigned WA[8] = {q0.x, q0.y, q0.z, q0.w, q1.x, q1.y, q1.z, q1.w};
    unsigned WB[8] = {q2.x, q2.y, q2.z, q2.w, q3.x, q3.y, q3.z, q3.w};

    #pragma unroll
    for (int w = 0; w < 8; ++w) {
        unsigned wa = WA[w], wb = WB[w];
        #pragma unroll
        for (int k = 0; k < 4; ++k) {
            // interleave byte k of wa (chain A) and wb (chain B): PRMT
            unsigned pr = __byte_perm(wa, wb, 0x0400 + k * 0x0101);
            __half2 v  = h2bits((pr & BMSK) | BIAS);     // {1024+va, 1024+vb}
            accR = __hadd2(accR, __heq2(v, p1h));
            accI = __hadd2(accI, __hgt2(v, p1h));
            accP = __hadd2(accP, __heq2(v, p2h));
            __half2 nz = __hne2(v, zero1024);            // 1.0 if nonzero
            accN = __hadd2(accN, nz);
            p2h = __hfma2(nz, __hsub2(p1h, p2h), p2h);   // exact blends
            p1h = __hfma2(nz, __hsub2(v,   p1h), p1h);
        }
    }

    // ---- Reduce across the 4 chunk lanes (half2 adds stay exact, <=256) ----
    #pragma unroll
    for (int m = 1; m <= 2; m <<= 1) {
        accR = __hadd2(accR, h2bits(__shfl_xor_sync(0xffffffffu, bitsh2(accR), m)));
        accI = __hadd2(accI, h2bits(__shfl_xor_sync(0xffffffffu, bitsh2(accI), m)));
        accP = __hadd2(accP, h2bits(__shfl_xor_sync(0xffffffffu, bitsh2(accP), m)));
        accN = __hadd2(accN, h2bits(__shfl_xor_sync(0xffffffffu, bitsh2(accN), m)));
    }

    if (c == 0) {
        float REP = __half2float(__low2half(accR)) + __half2float(__high2half(accR));
        float INC = __half2float(__low2half(accI)) + __half2float(__high2half(accI));
        float PER = __half2float(__low2half(accP)) + __half2float(__high2half(accP));
        float NF  = __half2float(__low2half(accN)) + __half2float(__high2half(accN));
        int   N   = (int)NF;
        float o0 = 0.f, o1 = 0.f, o2 = 0.f, o3 = 0.f;
        if (N > 1) {
            float DEC = (NF - 1.0f) - REP - INC;
            float d1  = 1.0f / (NF - 1.0f);
            o0 = REP * d1;
            o1 = INC * d1;
            o2 = DEC * d1;
            if (N >= 4) o3 = PER / (NF - 2.0f);
        }
        out[(long long)blockIdx.x * RPB + (tid >> 2)] =
            make_float4(o0, o1, o2, o3);
    }
}

extern "C" void kernel_launch(void* const* d_in, const int* in_sizes, int n_in,
                              void* d_out, int out_size)
{
    const int4* x = (const int4*)d_in[0];
    float4* out   = (float4*)d_out;
    const int total_elems = in_sizes[0];      // B * L
    const int nrows  = total_elems / L_LEN;   // 131072
    const int blocks = nrows / RPB;           // 2048
    pattern_kernel<<<blocks, TPB>>>(x, out);
}